// round 1
// baseline (speedup 1.0000x reference)
#include <cuda_runtime.h>
#include <stdint.h>

// CTC batch loss, prob-domain forward with power-of-2 rescaling.
// One warp per batch element; thread ln owns states [8*ln, 8*ln+8) (lane 31 also owns state 256).
// Probability rows staged gmem->smem via cp.async ring (16 stages, prefetch distance 15).

namespace {
constexpr int kB = 256, kT = 512, kC = 256, kL = 128;
constexpr int kBlank = kC - 1;          // 255
constexpr float kEps = 1e-7f;
constexpr int kDepth = 16;              // smem ring stages (power of 2)
constexpr int kPF = 15;                 // prefetch distance = kDepth - 1

__device__ __forceinline__ void cp_async16(uint32_t saddr, const float* g) {
    asm volatile("cp.async.cg.shared.global [%0], [%1], 16;" :: "r"(saddr), "l"(g));
}
__device__ __forceinline__ void cp_commit() {
    asm volatile("cp.async.commit_group;" ::: "memory");
}
template <int N>
__device__ __forceinline__ void cp_wait() {
    asm volatile("cp.async.wait_group %0;" :: "n"(N) : "memory");
}
} // namespace

__global__ void __launch_bounds__(32) ctc_loss_kernel(
    const int* __restrict__ y_true,     // [B, L] int32, values in [0, C-2]
    const float* __restrict__ y_pred,   // [B, T, C] float32 probabilities
    float* __restrict__ out)            // [B] float32 loss
{
    __shared__ __align__(16) float ring[kDepth][kC];

    const int b  = blockIdx.x;
    const int ln = threadIdx.x;

    // --- labels owned by this thread: label indices 4*ln .. 4*ln+3 ---
    const int4 lab4 = reinterpret_cast<const int4*>(y_true + (size_t)b * kL)[ln];
    const int lab0 = lab4.x, lab1 = lab4.y, lab2 = lab4.z, lab3 = lab4.w;
    const int labm1 = __shfl_up_sync(0xffffffffu, lab3, 1);  // label 4*ln-1 (junk on lane 0)

    // skip[s] for odd s = 2k+1: allowed iff k>=1 and label[k] != label[k-1]
    const float sk0 = (ln > 0 && lab0 != labm1) ? 1.f : 0.f;
    const float sk1 = (lab1 != lab0) ? 1.f : 0.f;
    const float sk2 = (lab2 != lab1) ? 1.f : 0.f;
    const float sk3 = (lab3 != lab2) ? 1.f : 0.f;

    // --- cp.async staging: thread ln copies bytes [32*ln, 32*ln+32) of each 1KB row ---
    const float*   gbase = y_pred + (size_t)b * kT * kC + ln * 8;
    const uint32_t sbase = (uint32_t)__cvta_generic_to_shared(&ring[0][0]) + (uint32_t)ln * 32u;

    // prologue: rows 0..kPF-1 (one commit group per row)
#pragma unroll
    for (int r = 0; r < kPF; r++) {
        uint32_t sa = sbase + (uint32_t)(r & (kDepth - 1)) * (kC * 4);
        const float* ga = gbase + (size_t)r * kC;
        cp_async16(sa, ga);
        cp_async16(sa + 16, ga + 4);
        cp_commit();
    }

    // alpha registers: a0..a7 = states 8*ln .. 8*ln+7 ; a8 = state 256 (real only on lane 31)
    float a0 = 0.f, a1 = 0.f, a2 = 0.f, a3 = 0.f, a4 = 0.f,
          a5 = 0.f, a6 = 0.f, a7 = 0.f, a8 = 0.f;
    int E = 0;  // accumulated base-2 exponent: true_alpha = stored_alpha * 2^E

    // ---- t = 0 : init ----
    cp_wait<kPF - 1>();
    __syncthreads();
    {
        const float* row = ring[0];
        float pb = row[kBlank] + kEps;
        float pl = row[lab0]   + kEps;
        if (ln == 0) { a0 = pb; a1 = pl; }  // only states 0 and 1 reachable at t=0
        // prefetch row kPF, keep the one-commit-per-iteration invariant
        const float* ga = gbase + (size_t)kPF * kC;
        uint32_t sa = sbase + (uint32_t)(kPF & (kDepth - 1)) * (kC * 4);
        cp_async16(sa, ga);
        cp_async16(sa + 16, ga + 4);
        cp_commit();
    }

    // ---- main recurrence: t = 1 .. T-1 ----
    for (int t = 1; t < kT; t++) {
        cp_wait<kPF - 1>();
        __syncthreads();
        const float* row = ring[t & (kDepth - 1)];

        float pb = row[kBlank] + kEps;   // blank prob (broadcast LDS)
        float p1 = row[lab0]   + kEps;
        float p3 = row[lab1]   + kEps;
        float p5 = row[lab2]   + kEps;
        float p7 = row[lab3]   + kEps;

        // halo: alpha[8*ln - 1] = previous lane's a7
        float h1 = __shfl_up_sync(0xffffffffu, a7, 1);
        if (ln == 0) h1 = 0.f;

        float n0 = (a0 + h1) * pb;
        float n1 = (a1 + fmaf(sk0, h1, a0)) * p1;
        float n2 = (a2 + a1) * pb;
        float n3 = (a3 + fmaf(sk1, a1, a2)) * p3;
        float n4 = (a4 + a3) * pb;
        float n5 = (a5 + fmaf(sk2, a3, a4)) * p5;
        float n6 = (a6 + a5) * pb;
        float n7 = (a7 + fmaf(sk3, a5, a6)) * p7;
        float n8 = (a8 + a7) * pb;       // state 256 (harmless bounded junk on lanes < 31)
        a0 = n0; a1 = n1; a2 = n2; a3 = n3; a4 = n4;
        a5 = n5; a6 = n6; a7 = n7; a8 = n8;

        // prefetch row t + kPF into stage (t-1) & 15 (already consumed)
        int r = t + kPF;
        if (r < kT) {
            const float* ga = gbase + (size_t)r * kC;
            uint32_t sa = sbase + (uint32_t)(r & (kDepth - 1)) * (kC * 4);
            cp_async16(sa, ga);
            cp_async16(sa + 16, ga + 4);
        }
        cp_commit();  // always commit (empty group ok) so wait_group count is invariant

        // rescale every 4 steps by 2^{-e}, e = exponent of warp max (exact bookkeeping, no MUFU)
        if ((t & 3) == 0) {
            float m = fmaxf(fmaxf(fmaxf(a0, a1), fmaxf(a2, a3)),
                            fmaxf(fmaxf(a4, a5), fmaxf(a6, fmaxf(a7, a8))));
#pragma unroll
            for (int o = 16; o; o >>= 1)
                m = fmaxf(m, __shfl_xor_sync(0xffffffffu, m, o));
            int eb = __float_as_int(m) >> 23;                 // biased exponent of m (m > 0, normal)
            float sc = __int_as_float((254 - eb) << 23);      // 2^(127 - eb) = 2^(-e)
            E += eb - 127;
            a0 *= sc; a1 *= sc; a2 *= sc; a3 *= sc; a4 *= sc;
            a5 *= sc; a6 *= sc; a7 *= sc; a8 *= sc;
        }
    }

    // loss = -log(alpha[S-1] + alpha[S-2]) ; states 256 and 255 live on lane 31
    if (ln == 31) {
        float tot  = a8 + a7;
        float loss = -(logf(tot) + (float)E * 0.6931471805599453f);
        out[b] = loss;
    }
}

extern "C" void kernel_launch(void* const* d_in, const int* in_sizes, int n_in,
                              void* d_out, int out_size) {
    const int* y_true;
    const float* y_pred;
    if (in_sizes[0] == kB * kL) {       // y_true is the 32768-element int32 input
        y_true = (const int*)d_in[0];
        y_pred = (const float*)d_in[1];
    } else {
        y_true = (const int*)d_in[1];
        y_pred = (const float*)d_in[0];
    }
    (void)n_in; (void)out_size;
    ctc_loss_kernel<<<kB, 32>>>(y_true, y_pred, (float*)d_out);
}

// round 2
// speedup vs baseline: 1.4462x; 1.4462x over previous
#include <cuda_runtime.h>
#include <stdint.h>

// CTC batch loss, prob-domain forward with lazy power-of-2 rescaling.
// One warp per batch element; thread ln owns states [8*ln, 8*ln+8) (lane 31 also owns state 256).
// Probability rows staged gmem->smem via cp.async ring (32 stages); gathered probs are
// software-pipelined one step ahead; warp max via redux.sync, applied 4 steps late.

namespace {
constexpr int kB = 256, kT = 512, kC = 256, kL = 128;
constexpr int kBlank = kC - 1;          // 255
constexpr float kEps = 1e-7f;
constexpr int kDepth = 32;              // smem ring stages (power of 2)
constexpr int kPF = 31;                 // prefetch distance = kDepth - 1

__device__ __forceinline__ void cp_async16(uint32_t saddr, const float* g) {
    asm volatile("cp.async.cg.shared.global [%0], [%1], 16;" :: "r"(saddr), "l"(g));
}
__device__ __forceinline__ void cp_commit() {
    asm volatile("cp.async.commit_group;" ::: "memory");
}
template <int N>
__device__ __forceinline__ void cp_wait() {
    asm volatile("cp.async.wait_group %0;" :: "n"(N) : "memory");
}
__device__ __forceinline__ uint32_t redux_max_u32(uint32_t v) {
    uint32_t r;
    asm volatile("redux.sync.max.u32 %0, %1, 0xffffffff;" : "=r"(r) : "r"(v));
    return r;
}
} // namespace

__global__ void __launch_bounds__(32) ctc_loss_kernel(
    const int* __restrict__ y_true,     // [B, L] int32, values in [0, C-2]
    const float* __restrict__ y_pred,   // [B, T, C] float32 probabilities
    float* __restrict__ out)            // [B] float32 loss
{
    __shared__ __align__(16) float ring[kDepth][kC];

    const int b  = blockIdx.x;
    const int ln = threadIdx.x;

    // --- labels owned by this thread: label indices 4*ln .. 4*ln+3 ---
    const int4 lab4 = reinterpret_cast<const int4*>(y_true + (size_t)b * kL)[ln];
    const int lab0 = lab4.x, lab1 = lab4.y, lab2 = lab4.z, lab3 = lab4.w;
    const int labm1 = __shfl_up_sync(0xffffffffu, lab3, 1);  // label 4*ln-1 (junk on lane 0)

    // skip[s] for odd s = 2k+1: allowed iff k>=1 and label[k] != label[k-1]
    const float sk0 = (ln > 0 && lab0 != labm1) ? 1.f : 0.f;
    const float sk1 = (lab1 != lab0) ? 1.f : 0.f;
    const float sk2 = (lab2 != lab1) ? 1.f : 0.f;
    const float sk3 = (lab3 != lab2) ? 1.f : 0.f;

    // --- cp.async staging: thread ln copies bytes [32*ln, 32*ln+32) of each 1KB row ---
    const float*   gbase = y_pred + (size_t)b * kT * kC + ln * 8;
    const uint32_t sbase = (uint32_t)__cvta_generic_to_shared(&ring[0][0]) + (uint32_t)ln * 32u;

    // prologue: rows 0..kPF-1 (one commit group per row)
    for (int r = 0; r < kPF; r++) {
        uint32_t sa = sbase + (uint32_t)(r & (kDepth - 1)) * (kC * 4);
        const float* ga = gbase + (size_t)r * kC;
        cp_async16(sa, ga);
        cp_async16(sa + 16, ga + 4);
        cp_commit();
    }

    // alpha regs: a0..a7 = states 8*ln..8*ln+7 ; a8 = state 256 (real only on lane 31)
    float a0 = 0.f, a1 = 0.f, a2 = 0.f, a3 = 0.f, a4 = 0.f,
          a5 = 0.f, a6 = 0.f, a7 = 0.f, a8 = 0.f;
    int   E = 0;                // applied base-2 exponent: true_alpha = stored * 2^E
    int   pendE = 0;            // lazily-applied rescale (measured one block earlier)
    float pendSc = 1.f;

    // current-step probs and next-step (prefetched) probs
    float pb, p1, p3, p5, p7;
    float nb, q1, q3, q5, q7;

    auto issue_row = [&](int r) {
        if (r < kT) {
            uint32_t sa = sbase + (uint32_t)(r & (kDepth - 1)) * (kC * 4);
            const float* ga = gbase + (size_t)r * kC;
            cp_async16(sa, ga);
            cp_async16(sa + 16, ga + 4);
        }
        cp_commit();  // always commit so the wait_group count stays invariant
    };
    auto load_row = [&](int t) {  // gather row t's probs into next regs
        cp_wait<kPF - 1>();
        __syncthreads();
        const float* row = ring[t & (kDepth - 1)];
        nb = row[kBlank] + kEps;
        q1 = row[lab0]   + kEps;
        q3 = row[lab1]   + kEps;
        q5 = row[lab2]   + kEps;
        q7 = row[lab3]   + kEps;
    };
    auto advance = [&]() { pb = nb; p1 = q1; p3 = q3; p5 = q5; p7 = q7; };

    auto recur = [&]() {
        float h1 = __shfl_up_sync(0xffffffffu, a7, 1);  // alpha[8*ln - 1]
        if (ln == 0) h1 = 0.f;
        float t0 = (a0 + h1) * pb;
        float t1 = (a1 + fmaf(sk0, h1, a0)) * p1;
        float t2 = (a2 + a1) * pb;
        float t3 = (a3 + fmaf(sk1, a1, a2)) * p3;
        float t4 = (a4 + a3) * pb;
        float t5 = (a5 + fmaf(sk2, a3, a4)) * p5;
        float t6 = (a6 + a5) * pb;
        float t7 = (a7 + fmaf(sk3, a5, a6)) * p7;
        float t8 = (a8 + a7) * pb;       // state 256 (bounded junk on lanes < 31)
        a0 = t0; a1 = t1; a2 = t2; a3 = t3; a4 = t4;
        a5 = t5; a6 = t6; a7 = t7; a8 = t8;
    };

    auto do_step = [&](int t, bool load_next) {
        issue_row(t + kPF);
        if (load_next) load_row(t + 1);   // prefetch: latency covered by recur below
        recur();
        if (load_next) advance();
    };

    // lazy rescale: apply last block's scale, then start a new warp-max reduction
    auto rescale = [&]() {
        a0 *= pendSc; a1 *= pendSc; a2 *= pendSc; a3 *= pendSc; a4 *= pendSc;
        a5 *= pendSc; a6 *= pendSc; a7 *= pendSc; a8 *= pendSc;
        E += pendE;
        float m = fmaxf(fmaxf(fmaxf(a0, a1), fmaxf(a2, a3)),
                        fmaxf(fmaxf(a4, a5), fmaxf(a6, fmaxf(a7, a8))));
        uint32_t mm = redux_max_u32(__float_as_uint(m));   // positive fp32: u32 order-preserving
        int eb = (int)(mm >> 23);                          // biased exponent of warp max
        pendSc = __int_as_float((uint32_t)(254 - eb) << 23);  // 2^(127 - eb)
        pendE  = eb - 127;
    };

    // ---- t = 0 : init ----
    cp_wait<kPF - 1>();
    __syncthreads();
    {
        const float* row = ring[0];
        pb = row[kBlank] + kEps;
        p1 = row[lab0]   + kEps;
    }
    issue_row(kPF);
    load_row(1);
    if (ln == 0) { a0 = pb; a1 = p1; }    // only states 0 and 1 reachable at t=0
    advance();

    do_step(1, true);
    do_step(2, true);
    do_step(3, true);

#pragma unroll 1
    for (int base = 4; base < 508; base += 4) {
        rescale();
        do_step(base,     true);
        do_step(base + 1, true);
        do_step(base + 2, true);
        do_step(base + 3, true);
    }
    rescale();
    do_step(508, true);
    do_step(509, true);
    do_step(510, true);
    do_step(511, false);

    // loss = -log(alpha[S-1] + alpha[S-2]); states 256 and 255 live on lane 31.
    // pendSc is intentionally unapplied: alphas are still in the E-scaled frame.
    if (ln == 31) {
        float tot = a8 + a7;
        out[b] = -(logf(tot) + (float)E * 0.6931471805599453f);
    }
}

extern "C" void kernel_launch(void* const* d_in, const int* in_sizes, int n_in,
                              void* d_out, int out_size) {
    const int* y_true;
    const float* y_pred;
    if (in_sizes[0] == kB * kL) {
        y_true = (const int*)d_in[0];
        y_pred = (const float*)d_in[1];
    } else {
        y_true = (const int*)d_in[1];
        y_pred = (const float*)d_in[0];
    }
    (void)n_in; (void)out_size;
    ctc_loss_kernel<<<kB, 32>>>(y_true, y_pred, (float*)d_out);
}